// round 13
// baseline (speedup 1.0000x reference)
#include <cuda_runtime.h>

// ---------------------------------------------------------------------------
// SparseConvolutionDownsample: rulebook sparse conv + BN + LeakyReLU
//   feats [1048576, 64] f32, W [4, 64, 128] f32, gamma/beta [128] f32,
//   in_idx/out_idx [4, 262144] i32, out [262144, 128] f32
//
// Round 13 (fixed round 12): output-binned, ATOMIC-FREE accumulation.
//   prepass: count -> scan -> scatter builds per-(bin,k) entry lists sorted
//   by local out-row. spconv: one CTA per 64-row bin accumulates everything
//   in a smem tile (warp-per-channel-group ownership; duplicate rows merged
//   via segmented shuffle-reduce), then writes out ONCE with STG (no REDs,
//   no zero_kernel) and fuses BN sum/sumsq.
// Fixes vs round 12:
//   * count/scatter grids: 4096 blocks (4*PNUM/256), NOT 16384 (OOB crash)
//   * cp.async drain at each k boundary (pad-group vs next-k slot-write race)
//   * cnt clamped to CAP
// ---------------------------------------------------------------------------

namespace {
constexpr int C_IN   = 64;
constexpr int C_OUT  = 128;
constexpr int PNUM   = 262144;            // = 2^18
constexpr int N_OUTR = 262144;
constexpr float BN_EPS = 1e-4f;
constexpr float LEAK   = 0.333f;

constexpr int BINROWS = 64;
constexpr int BINS  = N_OUTR / BINROWS;   // 4096
constexpr int SUBS  = BINS * 4;           // 16384 (bin, k) sub-bins
constexpr int CAP   = 128;                // entry capacity per sub-bin (mean 64)
constexpr int ROWF  = 68;                 // staged row stride (floats)
constexpr int RING  = 3;                  // cp.async ring depth
constexpr int APAD  = 132;                // acc row stride (floats)

constexpr int NCONTRIB = 4 * PNUM;        // 1048576 contributions
}

// scratch (device globals: zero-initialized at module load; bn_norm re-zeroes
// g_cnt2 at the end of every call so each invocation starts clean)
__device__ float g_stats2[2 * C_OUT];     // interleaved (sum, sumsq) per channel
__device__ int   g_cnt2[SUBS * 64];       // per (sub, local) counts
__device__ int   g_pos [SUBS * 64];       // scan offsets / running positions
__device__ int   g_cnt [SUBS];            // per-sub totals
__device__ int   g_entries[SUBS * CAP];   // (local << 18) | p, sorted by local

// f32 -> tf32 (round-to-nearest)
__device__ __forceinline__ unsigned tf32(float f) {
    unsigned r;
    asm("cvt.rna.tf32.f32 %0, %1;" : "=r"(r) : "f"(f));
    return r;
}

// ---------------------------------------------------------------------------
// P1: count contributions per (sub-bin, local); also zero g_stats2
// grid 4096 x 256 == NCONTRIB threads exactly
// ---------------------------------------------------------------------------
__global__ void count_kernel(const int* __restrict__ out_idx) {
    int idx = blockIdx.x * blockDim.x + threadIdx.x;    // 0 .. NCONTRIB-1
    int o   = __ldg(&out_idx[idx]);
    int k   = idx >> 18;
    int sub = ((o >> 6) << 2) | k;
    atomicAdd(&g_cnt2[(sub << 6) | (o & 63)], 1);
    if (idx < 2 * C_OUT) g_stats2[idx] = 0.f;
}

// ---------------------------------------------------------------------------
// P2: per-sub-bin exclusive scan of the 64 local counts (one warp per sub)
// ---------------------------------------------------------------------------
__global__ void scan_kernel() {
    int sub  = blockIdx.x * (blockDim.x >> 5) + (threadIdx.x >> 5);
    int lane = threadIdx.x & 31;
    int base = sub << 6;
    int c0 = g_cnt2[base + lane];
    int c1 = g_cnt2[base + 32 + lane];
    int s0 = c0, s1 = c1;
#pragma unroll
    for (int d = 1; d < 32; d <<= 1) {
        int t0 = __shfl_up_sync(0xffffffffu, s0, d);
        int t1 = __shfl_up_sync(0xffffffffu, s1, d);
        if (lane >= d) { s0 += t0; s1 += t1; }
    }
    int tot0 = __shfl_sync(0xffffffffu, s0, 31);
    g_pos[base + lane]      = s0 - c0;
    g_pos[base + 32 + lane] = tot0 + s1 - c1;
    if (lane == 31) g_cnt[sub] = tot0 + s1;
}

// ---------------------------------------------------------------------------
// P3: scatter entries into g_entries at their scanned positions
// grid 4096 x 256 == NCONTRIB threads exactly
// ---------------------------------------------------------------------------
__global__ void scatter_kernel(const int* __restrict__ out_idx) {
    int idx = blockIdx.x * blockDim.x + threadIdx.x;    // 0 .. NCONTRIB-1
    int o   = __ldg(&out_idx[idx]);
    int k   = idx >> 18;
    int p   = idx & (PNUM - 1);
    int sub = ((o >> 6) << 2) | k;
    int pos = atomicAdd(&g_pos[(sub << 6) | (o & 63)], 1);
    if (pos < CAP) g_entries[sub * CAP + pos] = ((o & 63) << 18) | p;
}

// ---------------------------------------------------------------------------
// segmented merge + race-free smem RMW.
// Fragment rows (gid 0..7) target acc row sl (equal values contiguous:
// sorted entries; zero-valued pads only ever ADD ZERO to row 0).
// 3-step segmented suffix-sum collapses duplicate rows; run heads do a plain
// ld/add/st on the smem accumulator. Cross-warp safe (channel-disjoint),
// within-warp safe (program-ordered smem ops).
// ---------------------------------------------------------------------------
__device__ __forceinline__ void seg_rmw(float* __restrict__ acc,
                                        float x, float y,
                                        int sl, int col, int gid) {
#pragma unroll
    for (int d = 1; d < 8; d <<= 1) {
        float xo = __shfl_down_sync(0xffffffffu, x,  4 * d);
        float yo = __shfl_down_sync(0xffffffffu, y,  4 * d);
        int   so = __shfl_down_sync(0xffffffffu, sl, 4 * d);
        if ((gid + d) < 8 && so == sl) { x += xo; y += yo; }
    }
    int su = __shfl_up_sync(0xffffffffu, sl, 4);
    if (gid == 0 || su != sl) {
        float2* a2 = reinterpret_cast<float2*>(&acc[sl * APAD + col]);
        float2 t = *a2;
        t.x += x; t.y += y;
        *a2 = t;
    }
}

// ---------------------------------------------------------------------------
// spconv: one CTA per bin. smem acc[64][APAD] holds the bin's out tile.
// Per k: load B frags, stream the sub-bin's sorted entries in 16-row batches
// (cp.async ring, zero-fill pads), MMA, seg-merged smem accumulate, then
// DRAIN all cp.async groups before the next k (slot-reuse race fix).
// Epilogue: fused BN sum/sumsq REDs + single STG.128 writeback.
// ---------------------------------------------------------------------------
__global__ __launch_bounds__(128, 4) void spconv_kernel(
    const float* __restrict__ feats,
    const float* __restrict__ W,
    const int*   __restrict__ in_idx,
    float*       __restrict__ out)
{
    __shared__ __align__(16) float acc[BINROWS * APAD];       // 33792 B
    __shared__ __align__(16) float sfeat[RING][16][ROWF];     // 13056 B
    __shared__ int slocal[RING][16];

    const int bin  = blockIdx.x;
    const int tid  = threadIdx.x;
    const int w    = tid >> 5;
    const int lane = tid & 31;
    const int gid  = lane >> 2;
    const int tig  = lane & 3;
    const int ch0  = w * 32;

    unsigned sbase;
    asm("{ .reg .u64 t; cvta.to.shared.u64 t, %1; cvt.u32.u64 %0, t; }"
        : "=r"(sbase) : "l"(&sfeat[0][0][0]));

    // zero the accumulator tile
    for (int t = tid; t < BINROWS * APAD / 4; t += 128)
        reinterpret_cast<float4*>(acc)[t] = make_float4(0.f, 0.f, 0.f, 0.f);
    __syncthreads();

    const int grow = tid >> 4;   // 0..7: this thread's gather row (x2 via c)
    const int gseg = tid & 15;   // 16B segment within the 256B row

    for (int k = 0; k < 4; k++) {
        const int sub   = (bin << 2) | k;
        int cnt         = __ldg(&g_cnt[sub]);
        if (cnt > CAP) cnt = CAP;              // capacity guard
        const int nb    = (cnt + 15) >> 4;
        const int ebase = sub * CAP;

        // ---- B fragments for this k ----
        const float* Wk = W + k * C_IN * C_OUT;
        unsigned b0[8][4], b1[8][4];
#pragma unroll
        for (int t = 0; t < 8; t++)
#pragma unroll
            for (int j = 0; j < 4; j++) {
                int col = ch0 + 8 * j + gid;
                b0[t][j] = tf32(__ldg(&Wk[(8 * t + tig)     * C_OUT + col]));
                b1[t][j] = tf32(__ldg(&Wk[(8 * t + tig + 4) * C_OUT + col]));
            }

        // issue batch n into ring slot n%RING (each thread: 2 rows x 16B)
        auto issue = [&](int n) {
            int slot = n % RING;
#pragma unroll
            for (int c = 0; c < 2; c++) {
                int row = grow + c * 8;          // rows 0..15
                int rb  = n * 16 + row;
                const float* src = feats;
                unsigned sz = 0;
                if (rb < cnt) {
                    int e  = __ldg(&g_entries[ebase + rb]);
                    int p  = e & 0x3FFFF;
                    int ii = __ldg(&in_idx[k * PNUM + p]);
                    src = feats + (size_t)ii * C_IN + gseg * 4;
                    sz  = 16;
                }
                unsigned dst = sbase + (unsigned)(slot * (16 * ROWF * 4)
                                                  + row * (ROWF * 4) + gseg * 16);
                asm volatile("cp.async.cg.shared.global [%0], [%1], 16, %2;"
                             :: "r"(dst), "l"(src), "r"(sz));
            }
            if (tid < 16) {
                int rb2 = n * 16 + tid;
                int sl  = 0;
                if (rb2 < cnt) sl = (__ldg(&g_entries[ebase + rb2]) >> 18) & 63;
                slocal[slot][tid] = sl;
            }
            asm volatile("cp.async.commit_group;" ::: "memory");
        };

        issue(0);
        issue(1);

        for (int n = 0; n < nb; n++) {
            issue(n + 2);   // zero-fill past the end; keeps group accounting exact
            asm volatile("cp.async.wait_group 2;" ::: "memory");
            __syncthreads();

            const int slot = n % RING;
            const float* sr0 = &sfeat[slot][gid][0];
            const float* sr8 = &sfeat[slot][gid + 8][0];
            unsigned a[8][4];
#pragma unroll
            for (int t = 0; t < 8; t++) {
                a[t][0] = tf32(sr0[8 * t + tig]);
                a[t][1] = tf32(sr8[8 * t + tig]);
                a[t][2] = tf32(sr0[8 * t + tig + 4]);
                a[t][3] = tf32(sr8[8 * t + tig + 4]);
            }
            const int slA = slocal[slot][gid];
            const int slB = slocal[slot][gid + 8];

#pragma unroll
            for (int j = 0; j < 4; j++) {
                float c0 = 0.f, c1 = 0.f, c2 = 0.f, c3 = 0.f;
#pragma unroll
                for (int t = 0; t < 8; t++) {
                    asm("mma.sync.aligned.m16n8k8.row.col.f32.tf32.tf32.f32 "
                        "{%0,%1,%2,%3}, {%4,%5,%6,%7}, {%8,%9}, {%0,%1,%2,%3};"
                        : "+f"(c0), "+f"(c1), "+f"(c2), "+f"(c3)
                        : "r"(a[t][0]), "r"(a[t][1]), "r"(a[t][2]), "r"(a[t][3]),
                          "r"(b0[t][j]), "r"(b1[t][j]));
                }
                int col = ch0 + 8 * j + 2 * tig;
                seg_rmw(acc, c0, c1, slA, col, gid);   // rows 0..7 of tile
                seg_rmw(acc, c2, c3, slB, col, gid);   // rows 8..15 of tile
            }
            __syncthreads();
        }

        // drain the 2 trailing pad groups so next k's slot writes can't race
        asm volatile("cp.async.wait_group 0;" ::: "memory");
        __syncthreads();
    }

    // ---- fused BN stats: thread owns channel tid ----
    {
        float s = 0.f, q = 0.f;
#pragma unroll 8
        for (int r = 0; r < BINROWS; r++) {
            float v = acc[r * APAD + tid];
            s += v; q += v * v;
        }
        asm volatile("red.global.add.v2.f32 [%0], {%1, %2};"
                     :: "l"(&g_stats2[2 * tid]), "f"(s), "f"(q) : "memory");
    }

    // ---- single coalesced writeback (no atomics, no prior zeroing) ----
    {
        const int cg = tid & 31, rs = tid >> 5;
#pragma unroll
        for (int r = rs; r < BINROWS; r += 4) {
            float4 v = *reinterpret_cast<float4*>(&acc[r * APAD + 4 * cg]);
            *reinterpret_cast<float4*>(
                &out[((size_t)(bin * BINROWS + r)) * C_OUT + 4 * cg]) = v;
        }
    }
}

// ---------------------------------------------------------------------------
// bn_norm: normalize + LeakyReLU in place; resets g_cnt2 for the next call
// ---------------------------------------------------------------------------
__global__ void bn_norm_kernel(float4* __restrict__ out,
                               const float* __restrict__ gamma,
                               const float* __restrict__ beta) {
    __shared__ float sc[C_OUT], sf[C_OUT];
    if (threadIdx.x < C_OUT) {
        int c = threadIdx.x;
        const float inv = 1.f / (float)N_OUTR;
        float mean = g_stats2[2 * c] * inv;
        float var  = g_stats2[2 * c + 1] * inv - mean * mean;
        float s    = gamma[c] * rsqrtf(var + BN_EPS);
        sc[c] = s;
        sf[c] = beta[c] - mean * s;
    }
    __syncthreads();

    const size_t n = (size_t)N_OUTR * (C_OUT / 4);
    const size_t stride = (size_t)gridDim.x * blockDim.x;
    const size_t gtid = (size_t)blockIdx.x * blockDim.x + threadIdx.x;
    for (size_t i = gtid; i < n; i += stride) {
        int c0 = ((int)(i & 31)) * 4;
        float4 v = out[i];
        v.x = v.x * sc[c0 + 0] + sf[c0 + 0];
        v.y = v.y * sc[c0 + 1] + sf[c0 + 1];
        v.z = v.z * sc[c0 + 2] + sf[c0 + 2];
        v.w = v.w * sc[c0 + 3] + sf[c0 + 3];
        v.x = (v.x >= 0.f) ? v.x : v.x * LEAK;
        v.y = (v.y >= 0.f) ? v.y : v.y * LEAK;
        v.z = (v.z >= 0.f) ? v.z : v.z * LEAK;
        v.w = (v.w >= 0.f) ? v.w : v.w * LEAK;
        out[i] = v;
    }
    // reset per-(sub,local) counters so the next invocation starts clean
    for (size_t i = gtid; i < (size_t)SUBS * 64; i += stride)
        g_cnt2[i] = 0;
}

// ---------------------------------------------------------------------------
// Launch: inputs per metadata order:
//   0 feats, 1 W, 2 gamma, 3 beta, 4 in_idx, 5 out_idx, 6 n_out (ignored)
// Launch order puts spconv at global index 5 (harness issues 2 launches
// before ours) so ncu (-s 5 -c 1) profiles it.
// ---------------------------------------------------------------------------
extern "C" void kernel_launch(void* const* d_in, const int* in_sizes, int n_in,
                              void* d_out, int out_size) {
    const float* feats   = (const float*)d_in[0];
    const float* W       = (const float*)d_in[1];
    const float* gamma   = (const float*)d_in[2];
    const float* beta    = (const float*)d_in[3];
    const int*   in_idx  = (const int*)d_in[4];
    const int*   out_idx = (const int*)d_in[5];
    float* out = (float*)d_out;

    count_kernel  <<<NCONTRIB / 256, 256>>>(out_idx);
    scan_kernel   <<<SUBS / 8, 256>>>();
    scatter_kernel<<<NCONTRIB / 256, 256>>>(out_idx);
    spconv_kernel <<<BINS, 128>>>(feats, W, in_idx, out);
    bn_norm_kernel<<<1024, 256>>>((float4*)out, gamma, beta);
}